// round 1
// baseline (speedup 1.0000x reference)
#include <cuda_runtime.h>
#include <cstdint>
#include <cstddef>

#define HH 1024
#define TT 256
#define BB 64
#define BT (BB*TT)       /* 16384 */
#define G4 (4*HH)        /* 4096 */
#define NBLK_REC 128

// ------------------------- scratch (device globals; no cudaMalloc allowed) ---
__device__ float g_gates[(size_t)BT * G4];   // 256 MB: gate/xg scratch
__device__ float g_h1[(size_t)BT * HH];      // 64 MB
__device__ float g_h2[(size_t)BT * HH];      // 64 MB
__device__ float g_hbuf[2 * BB * HH];        // recurrent h double buffer
__device__ float g_cst[BB * HH];             // recurrent c state
__device__ float g_z1[BB * HH];
__device__ float g_z2[BB * (HH/2)];
__device__ volatile unsigned g_cnt = 0;
__device__ volatile unsigned g_sense = 0;

// ------------------------- helpers ------------------------------------------
__device__ __forceinline__ float tf32r(float x) {
    uint32_t u;
    asm("cvt.rna.tf32.f32 %0, %1;" : "=r"(u) : "f"(x));
    return __uint_as_float(u);
}
__device__ __forceinline__ uint32_t fbits(float x) { return __float_as_uint(x); }

__device__ __forceinline__ void mma_tf32(float c[4],
                                         uint32_t a0, uint32_t a1, uint32_t a2, uint32_t a3,
                                         uint32_t b0, uint32_t b1) {
    asm volatile(
        "mma.sync.aligned.m16n8k8.row.col.f32.tf32.tf32.f32 "
        "{%0,%1,%2,%3}, {%4,%5,%6,%7}, {%8,%9}, {%0,%1,%2,%3};"
        : "+f"(c[0]), "+f"(c[1]), "+f"(c[2]), "+f"(c[3])
        : "r"(a0), "r"(a1), "r"(a2), "r"(a3), "r"(b0), "r"(b1));
}

__device__ __forceinline__ float sigf(float x) { return 1.0f / (1.0f + expf(-x)); }

// ------------------------- generic tf32 GEMM: C = A @ W^T + bias ------------
// A: M x K, row stride asr (elements). W: N x K row-major. C: M x N row-major.
// BM=128, BN=128, BK=16, 256 threads (8 warps: 2(M) x 4(N), warp tile 64x32).
template<int RELU>
__launch_bounds__(256, 1)
__global__ void gemm_kernel(const float* __restrict__ A, long long asr,
                            const float* __restrict__ W,
                            const float* __restrict__ b1p, const float* __restrict__ b2p,
                            float* __restrict__ C, int M, int N, int K)
{
    __shared__ float As[2][128][20];
    __shared__ float Bs[2][128][20];

    const int tid  = threadIdx.x;
    const int lane = tid & 31, warp = tid >> 5;
    const int wm = warp >> 2, wn = warp & 3;
    const int mb = blockIdx.y * 128, nb = blockIdx.x * 128;

    const int lrow = tid >> 2;          // 0..63
    const int lkc  = (tid & 3) * 4;     // 0,4,8,12

    float acc[4][4][4];
#pragma unroll
    for (int a = 0; a < 4; a++)
#pragma unroll
        for (int b = 0; b < 4; b++)
#pragma unroll
            for (int c = 0; c < 4; c++) acc[a][b][c] = 0.0f;

    const int KT = K >> 4;
    float4 ra0, ra1, rb0, rb1;

    auto fetch = [&](int kt) {
        const int k0 = kt * 16 + lkc;
        const int r0 = mb + lrow, r1 = mb + lrow + 64;
        ra0 = (r0 < M) ? *(const float4*)(A + (size_t)r0 * asr + k0) : make_float4(0,0,0,0);
        ra1 = (r1 < M) ? *(const float4*)(A + (size_t)r1 * asr + k0) : make_float4(0,0,0,0);
        rb0 = *(const float4*)(W + (size_t)(nb + lrow)      * K + k0);
        rb1 = *(const float4*)(W + (size_t)(nb + lrow + 64) * K + k0);
    };
    auto stage = [&](int buf) {
        float* a0 = &As[buf][lrow][lkc];
        a0[0]=tf32r(ra0.x); a0[1]=tf32r(ra0.y); a0[2]=tf32r(ra0.z); a0[3]=tf32r(ra0.w);
        float* a1 = &As[buf][lrow+64][lkc];
        a1[0]=tf32r(ra1.x); a1[1]=tf32r(ra1.y); a1[2]=tf32r(ra1.z); a1[3]=tf32r(ra1.w);
        float* b0 = &Bs[buf][lrow][lkc];
        b0[0]=tf32r(rb0.x); b0[1]=tf32r(rb0.y); b0[2]=tf32r(rb0.z); b0[3]=tf32r(rb0.w);
        float* b1 = &Bs[buf][lrow+64][lkc];
        b1[0]=tf32r(rb1.x); b1[1]=tf32r(rb1.y); b1[2]=tf32r(rb1.z); b1[3]=tf32r(rb1.w);
    };
    auto compute = [&](int buf) {
#pragma unroll
        for (int kk = 0; kk < 16; kk += 8) {
            uint32_t af[4][4], bf[4][2];
#pragma unroll
            for (int mt = 0; mt < 4; mt++) {
                const int r = wm * 64 + mt * 16 + (lane >> 2);
                const int c = kk + (lane & 3);
                af[mt][0] = fbits(As[buf][r][c]);
                af[mt][1] = fbits(As[buf][r + 8][c]);
                af[mt][2] = fbits(As[buf][r][c + 4]);
                af[mt][3] = fbits(As[buf][r + 8][c + 4]);
            }
#pragma unroll
            for (int nt = 0; nt < 4; nt++) {
                const int n = wn * 32 + nt * 8 + (lane >> 2);
                bf[nt][0] = fbits(Bs[buf][n][kk + (lane & 3)]);
                bf[nt][1] = fbits(Bs[buf][n][kk + (lane & 3) + 4]);
            }
#pragma unroll
            for (int mt = 0; mt < 4; mt++)
#pragma unroll
                for (int nt = 0; nt < 4; nt++)
                    mma_tf32(acc[mt][nt], af[mt][0], af[mt][1], af[mt][2], af[mt][3],
                             bf[nt][0], bf[nt][1]);
        }
    };

    fetch(0); stage(0); __syncthreads();
    for (int kt = 0; kt < KT; ++kt) {
        const int buf = kt & 1;
        if (kt + 1 < KT) fetch(kt + 1);
        compute(buf);
        if (kt + 1 < KT) stage(buf ^ 1);
        __syncthreads();
    }

    // epilogue
#pragma unroll
    for (int mt = 0; mt < 4; mt++) {
#pragma unroll
        for (int nt = 0; nt < 4; nt++) {
            const int row0 = mb + wm * 64 + mt * 16 + (lane >> 2);
            const int col  = nb + wn * 32 + nt * 8 + 2 * (lane & 3);
            const float b0v = (b1p ? b1p[col]     : 0.f) + (b2p ? b2p[col]     : 0.f);
            const float b1v = (b1p ? b1p[col + 1] : 0.f) + (b2p ? b2p[col + 1] : 0.f);
            float v0 = acc[mt][nt][0] + b0v, v1 = acc[mt][nt][1] + b1v;
            float v2 = acc[mt][nt][2] + b0v, v3 = acc[mt][nt][3] + b1v;
            if (RELU) {
                v0 = fmaxf(v0, 0.f); v1 = fmaxf(v1, 0.f);
                v2 = fmaxf(v2, 0.f); v3 = fmaxf(v3, 0.f);
            }
            if (row0 < M) *(float2*)(C + (size_t)row0 * N + col) = make_float2(v0, v1);
            if (row0 + 8 < M) *(float2*)(C + (size_t)(row0 + 8) * N + col) = make_float2(v2, v3);
        }
    }
}

// ------------------------- lstm1 elementwise (f gate unused) -----------------
__global__ void ew_lstm1_kernel(const float* __restrict__ G, float* __restrict__ h)
{
    const size_t idx = (size_t)blockIdx.x * blockDim.x + threadIdx.x; // < BT*HH
    const int r = (int)(idx >> 10), n = (int)(idx & 1023);
    const float* gr = G + (size_t)r * G4;
    const float gi = gr[n], gg = gr[2048 + n], go = gr[3072 + n];
    const float c = sigf(gi) * tanhf(gg);
    h[idx] = sigf(go) * tanhf(c);
}

// ------------------------- grid barrier (128 resident CTAs) -----------------
__device__ __forceinline__ void grid_bar()
{
    __threadfence();
    __syncthreads();
    if (threadIdx.x == 0) {
        const unsigned gen = g_sense;
        const unsigned arrived = atomicAdd((unsigned*)&g_cnt, 1u);
        if (arrived == NBLK_REC - 1u) {
            g_cnt = 0;
            __threadfence();
            atomicAdd((unsigned*)&g_sense, 1u);
        } else {
            while (g_sense == gen) { __nanosleep(64); }
        }
        __threadfence();
    }
    __syncthreads();
}

// ------------------------- recurrent LSTM layer ------------------------------
// 128 CTAs x 256 threads. CTA b owns h columns n0=8b..n0+7 (32 gate columns).
// Whh slab (tf32) lives in SMEM for all 256 steps; h streamed per step in 4
// SMEM chunks of K=256. One grid barrier per step.
__launch_bounds__(256, 1)
__global__ void recur_kernel(const float* __restrict__ xg,   // [BT, 4096] (+biases)
                             const float* __restrict__ Whh,  // [4096, 1024]
                             float* __restrict__ hs,         // [BT, 1024]
                             float* __restrict__ hbuf,       // [2, 64, 1024]
                             float* __restrict__ cst)        // [64, 1024]
{
    extern __shared__ float sm[];
    float* Ws = sm;                   // [32][1028] tf32 weights
    float* hS = sm + 32 * 1028;       // [64][260]  tf32 h chunk
    float* gS = hS;                   // [64][33]   gate exchange (reuses hS)

    const int tid = threadIdx.x, lane = tid & 31, warp = tid >> 5;
    const int wm = warp >> 1, wn = warp & 1;        // 4(M) x 2(N)
    const int n0 = blockIdx.x * 8;

    // load Whh slab: packed row c = g*8 + j  ->  Whh[g*1024 + n0 + j]
#pragma unroll 1
    for (int c = 0; c < 32; c++) {
        const int g = c >> 3, j = c & 7;
        const float4 v = *(const float4*)(Whh + ((size_t)(g * HH + n0 + j)) * HH + tid * 4);
        float* d = Ws + c * 1028 + tid * 4;
        d[0] = tf32r(v.x); d[1] = tf32r(v.y); d[2] = tf32r(v.z); d[3] = tf32r(v.w);
    }
    __syncthreads();

    const int arow = wm * 16 + (lane >> 2);
    const int kofs = lane & 3;

    for (int t = 0; t < TT; t++) {
        float acc[2][4] = {{0,0,0,0},{0,0,0,0}};

        if (t > 0) {
            const float* hsrc = hbuf + (size_t)(t & 1) * (BB * HH);
#pragma unroll 1
            for (int ch = 0; ch < 4; ++ch) {
                __syncthreads();   // protect hS reuse
#pragma unroll
                for (int v = tid; v < 4096; v += 256) {
                    const int r = v >> 6, kc = (v & 63) * 4;
                    const float4 x = *(const float4*)(hsrc + r * HH + ch * 256 + kc);
                    float* d = hS + r * 260 + kc;
                    d[0] = tf32r(x.x); d[1] = tf32r(x.y); d[2] = tf32r(x.z); d[3] = tf32r(x.w);
                }
                __syncthreads();
#pragma unroll
                for (int ks = 0; ks < 32; ++ks) {
                    const int kk = ks * 8;
                    const uint32_t a0 = fbits(hS[arow * 260 + kk + kofs]);
                    const uint32_t a1 = fbits(hS[(arow + 8) * 260 + kk + kofs]);
                    const uint32_t a2 = fbits(hS[arow * 260 + kk + kofs + 4]);
                    const uint32_t a3 = fbits(hS[(arow + 8) * 260 + kk + kofs + 4]);
#pragma unroll
                    for (int nt = 0; nt < 2; nt++) {
                        const int ncol = wn * 16 + nt * 8 + (lane >> 2);
                        const int kg = ch * 256 + kk + kofs;
                        const uint32_t b0 = fbits(Ws[ncol * 1028 + kg]);
                        const uint32_t b1 = fbits(Ws[ncol * 1028 + kg + 4]);
                        mma_tf32(acc[nt], a0, a1, a2, a3, b0, b1);
                    }
                }
            }
            __syncthreads();  // before gS overwrites the hS region
        }

        // write gate tile to SMEM for cross-warp exchange
        {
            const int r0 = wm * 16 + (lane >> 2);
#pragma unroll
            for (int nt = 0; nt < 2; nt++) {
                const int c0 = wn * 16 + nt * 8 + 2 * (lane & 3);
                gS[r0 * 33 + c0]           = acc[nt][0];
                gS[r0 * 33 + c0 + 1]       = acc[nt][1];
                gS[(r0 + 8) * 33 + c0]     = acc[nt][2];
                gS[(r0 + 8) * 33 + c0 + 1] = acc[nt][3];
            }
        }
        __syncthreads();

        // gate combine + state update (512 outputs, 2/thread)
#pragma unroll
        for (int e = tid; e < 512; e += 256) {
            const int r = e >> 3, j = e & 7;
            const size_t xrow = ((size_t)(r * TT + t)) * G4 + n0 + j;
            const float gi = gS[r * 33 + j]      + xg[xrow];
            const float gf = gS[r * 33 + 8 + j]  + xg[xrow + 1024];
            const float gg = gS[r * 33 + 16 + j] + xg[xrow + 2048];
            const float go = gS[r * 33 + 24 + j] + xg[xrow + 3072];
            const float cp = (t == 0) ? 0.f : cst[r * HH + n0 + j];
            const float cn = sigf(gf) * cp + sigf(gi) * tanhf(gg);
            const float hn = sigf(go) * tanhf(cn);
            cst[r * HH + n0 + j] = cn;
            hbuf[(size_t)((t + 1) & 1) * (BB * HH) + r * HH + n0 + j] = hn;
            hs[((size_t)(r * TT + t)) * HH + n0 + j] = hn;
        }

        if (t < TT - 1) grid_bar();
    }
}

// ------------------------- final MLP layer 3 ---------------------------------
__global__ void mlp3_kernel(const float* __restrict__ z2, const float* __restrict__ W3,
                            const float* __restrict__ b3, float* __restrict__ out)
{
    __shared__ float red[8];
    const int b = blockIdx.x;
    float s = 0.f;
    for (int k = threadIdx.x; k < 512; k += 256) s += z2[b * 512 + k] * W3[k];
#pragma unroll
    for (int o = 16; o; o >>= 1) s += __shfl_down_sync(0xffffffffu, s, o);
    if ((threadIdx.x & 31) == 0) red[threadIdx.x >> 5] = s;
    __syncthreads();
    if (threadIdx.x < 8) {
        s = red[threadIdx.x];
#pragma unroll
        for (int o = 4; o; o >>= 1) s += __shfl_down_sync(0xffu, s, o);
        if (threadIdx.x == 0) out[b] = s + b3[0];
    }
}

// ------------------------- launcher ------------------------------------------
extern "C" void kernel_launch(void* const* d_in, const int* in_sizes, int n_in,
                              void* d_out, int out_size)
{
    const float* xx       = (const float*)d_in[0];
    const float* l1_Wih0  = (const float*)d_in[1];
    const float* l1_bih0  = (const float*)d_in[2];
    const float* l1_bhh0  = (const float*)d_in[3];
    const float* l1_Wih1  = (const float*)d_in[4];
    const float* l1_bih1  = (const float*)d_in[5];
    const float* l1_bhh1  = (const float*)d_in[6];
    const float* l2_Wih0  = (const float*)d_in[7];
    const float* l2_Whh0  = (const float*)d_in[8];
    const float* l2_bih0  = (const float*)d_in[9];
    const float* l2_bhh0  = (const float*)d_in[10];
    const float* l2_Wih1  = (const float*)d_in[11];
    const float* l2_Whh1  = (const float*)d_in[12];
    const float* l2_bih1  = (const float*)d_in[13];
    const float* l2_bhh1  = (const float*)d_in[14];
    const float* mlp_W1   = (const float*)d_in[15];
    const float* mlp_b1   = (const float*)d_in[16];
    const float* mlp_W2   = (const float*)d_in[17];
    const float* mlp_b2   = (const float*)d_in[18];
    const float* mlp_W3   = (const float*)d_in[19];
    const float* mlp_b3   = (const float*)d_in[20];
    float* out = (float*)d_out;

    void* p;
    cudaGetSymbolAddress(&p, g_gates); float* gates = (float*)p;
    cudaGetSymbolAddress(&p, g_h1);    float* h1    = (float*)p;
    cudaGetSymbolAddress(&p, g_h2);    float* h2    = (float*)p;
    cudaGetSymbolAddress(&p, g_hbuf);  float* hbuf  = (float*)p;
    cudaGetSymbolAddress(&p, g_cst);   float* cst   = (float*)p;
    cudaGetSymbolAddress(&p, g_z1);    float* z1    = (float*)p;
    cudaGetSymbolAddress(&p, g_z2);    float* z2    = (float*)p;

    const int recur_smem = (32 * 1028 + 64 * 260) * 4;  // 198144 B
    cudaFuncSetAttribute(recur_kernel, cudaFuncAttributeMaxDynamicSharedMemorySize, recur_smem);

    const dim3 blk(256);
    const dim3 gBig(G4 / 128, BT / 128);     // 32 x 128
    const int ewBlocks = (BT * HH) / 256;    // 65536

    // lstm1 layer 0: gates = xx @ W^T + b   (M=16384, N=4096, K=256)
    gemm_kernel<0><<<gBig, blk>>>(xx, 256, l1_Wih0, l1_bih0, l1_bhh0, gates, BT, G4, 256);
    ew_lstm1_kernel<<<ewBlocks, blk>>>(gates, h1);

    // lstm1 layer 1 (K=1024)
    gemm_kernel<0><<<gBig, blk>>>(h1, HH, l1_Wih1, l1_bih1, l1_bhh1, gates, BT, G4, HH);
    ew_lstm1_kernel<<<ewBlocks, blk>>>(gates, h2);

    // lstm2 layer 0: xg then recurrence
    gemm_kernel<0><<<gBig, blk>>>(h2, HH, l2_Wih0, l2_bih0, l2_bhh0, gates, BT, G4, HH);
    recur_kernel<<<NBLK_REC, blk, recur_smem>>>(gates, l2_Whh0, h1, hbuf, cst);

    // lstm2 layer 1
    gemm_kernel<0><<<gBig, blk>>>(h1, HH, l2_Wih1, l2_bih1, l2_bhh1, gates, BT, G4, HH);
    recur_kernel<<<NBLK_REC, blk, recur_smem>>>(gates, l2_Whh1, h2, hbuf, cst);

    // MLP on last timestep: A = h2 rows (b*T + 255), row stride T*H
    gemm_kernel<1><<<dim3(HH / 128, 1), blk>>>(h2 + (size_t)(TT - 1) * HH, (long long)TT * HH,
                                               mlp_W1, mlp_b1, nullptr, z1, BB, HH, HH);
    gemm_kernel<1><<<dim3((HH / 2) / 128, 1), blk>>>(z1, HH, mlp_W2, mlp_b2, nullptr,
                                                     z2, BB, HH / 2, HH);
    mlp3_kernel<<<BB, blk>>>(z2, mlp_W3, mlp_b3, out);
}

// round 2
// speedup vs baseline: 1.2861x; 1.2861x over previous
#include <cuda_runtime.h>
#include <cuda_bf16.h>
#include <cstdint>
#include <cstddef>

#define HH 1024
#define TT 256
#define BB 64
#define BT (BB*TT)       /* 16384 */
#define G4 (4*HH)        /* 4096 */
#define NBLK_REC 128

#define ASTRIDE 20
#define STAGE_ELEMS (128*ASTRIDE)   /* 2560 floats per tile stage */

#define RC_CH  16      /* recurrence: chunks per step   */
#define RC_CK  64      /* K per chunk                   */
#define RC_PAD 68      /* padded row stride (floats)    */
#define RC_BUFE (64*RC_PAD)

// ------------------------- scratch (device globals; no cudaMalloc allowed) ---
__device__ __align__(256) float g_gates[(size_t)BT * G4];   // 256 MB xg scratch (lstm2)
__device__ __align__(256) float g_h1[(size_t)BT * HH];      // 64 MB
__device__ __align__(256) float g_h2[(size_t)BT * HH];      // 64 MB
__device__ __align__(256) float g_hbuf[2 * BB * HH];        // recurrent h double buffer
__device__ __align__(256) float g_z1[BB * HH];
__device__ __align__(256) float g_z2[BB * (HH/2)];
__device__ volatile unsigned g_cnt = 0;
__device__ volatile unsigned g_sense = 0;

// ------------------------- helpers ------------------------------------------
__device__ __forceinline__ float tf32r(float x) {
    uint32_t u;
    asm("cvt.rna.tf32.f32 %0, %1;" : "=r"(u) : "f"(x));
    return __uint_as_float(u);
}
__device__ __forceinline__ uint32_t fbits(float x) { return __float_as_uint(x); }

__device__ __forceinline__ void mma_tf32(float c[4],
                                         uint32_t a0, uint32_t a1, uint32_t a2, uint32_t a3,
                                         uint32_t b0, uint32_t b1) {
    asm volatile(
        "mma.sync.aligned.m16n8k8.row.col.f32.tf32.tf32.f32 "
        "{%0,%1,%2,%3}, {%4,%5,%6,%7}, {%8,%9}, {%0,%1,%2,%3};"
        : "+f"(c[0]), "+f"(c[1]), "+f"(c[2]), "+f"(c[3])
        : "r"(a0), "r"(a1), "r"(a2), "r"(a3), "r"(b0), "r"(b1));
}

__device__ __forceinline__ float sigf(float x) { return 1.0f / (1.0f + expf(-x)); }

__device__ __forceinline__ void cp16(uint32_t dsh, const void* src) {
    asm volatile("cp.async.cg.shared.global [%0], [%1], 16;" :: "r"(dsh), "l"(src));
}
__device__ __forceinline__ void cp_commit() { asm volatile("cp.async.commit_group;"); }

// ------------------------- pipelined tf32 tile accumulate --------------------
// acc += A[mb:mb+128, :K] @ Wslab[0:128, :K]^T   (W rows are output columns)
// 4-stage cp.async pipeline, BK=16, 8 warps (2M x 4N), warp tile 64x32.
__device__ __forceinline__ void run_gemm_acc(
    const float* __restrict__ A, long long asr, int M, int mb,
    const float* __restrict__ Wslab, int K,
    float* As, float* Bs, float (&acc)[4][4][4])
{
    const int tid  = threadIdx.x;
    const int lane = tid & 31, warp = tid >> 5;
    const int wm = warp >> 2, wn = warp & 3;
    const int lrow = tid >> 2;          // 0..63
    const int lkc  = (tid & 3) * 4;     // 0,4,8,12

    int r0 = mb + lrow;      if (r0 > M - 1) r0 = M - 1;
    int r1 = mb + lrow + 64; if (r1 > M - 1) r1 = M - 1;
    const float* a0p = A + (size_t)r0 * asr + lkc;
    const float* a1p = A + (size_t)r1 * asr + lkc;
    const float* b0p = Wslab + (size_t)lrow * K + lkc;
    const float* b1p = Wslab + (size_t)(lrow + 64) * K + lkc;

    const uint32_t sA  = (uint32_t)__cvta_generic_to_shared(As) + (uint32_t)((lrow * ASTRIDE + lkc) * 4);
    const uint32_t sA2 = sA + 64 * ASTRIDE * 4;
    const uint32_t sB  = (uint32_t)__cvta_generic_to_shared(Bs) + (uint32_t)((lrow * ASTRIDE + lkc) * 4);
    const uint32_t sB2 = sB + 64 * ASTRIDE * 4;

    const int KT = K >> 4;

    auto issue = [&](int kt) {
        const int slot = kt & 3;
        const int koff = kt * 16;
        const uint32_t so = (uint32_t)(slot * STAGE_ELEMS * 4);
        cp16(sA  + so, a0p + koff);
        cp16(sA2 + so, a1p + koff);
        cp16(sB  + so, b0p + koff);
        cp16(sB2 + so, b1p + koff);
        cp_commit();
    };

    const int pre = KT < 3 ? KT : 3;
    for (int s = 0; s < pre; ++s) issue(s);

    for (int kt = 0; kt < KT; ++kt) {
        if (kt < KT - 2)       asm volatile("cp.async.wait_group 2;");
        else if (kt == KT - 2) asm volatile("cp.async.wait_group 1;");
        else                   asm volatile("cp.async.wait_group 0;");
        __syncthreads();
        if (kt + 3 < KT) issue(kt + 3);

        const float* Ab = As + (kt & 3) * STAGE_ELEMS;
        const float* Bb = Bs + (kt & 3) * STAGE_ELEMS;
#pragma unroll
        for (int kk = 0; kk < 16; kk += 8) {
            uint32_t af[4][4], bfr[4][2];
#pragma unroll
            for (int mt = 0; mt < 4; mt++) {
                const int r = wm * 64 + mt * 16 + (lane >> 2);
                const int c = kk + (lane & 3);
                af[mt][0] = fbits(Ab[r * ASTRIDE + c]);
                af[mt][1] = fbits(Ab[(r + 8) * ASTRIDE + c]);
                af[mt][2] = fbits(Ab[r * ASTRIDE + c + 4]);
                af[mt][3] = fbits(Ab[(r + 8) * ASTRIDE + c + 4]);
            }
#pragma unroll
            for (int nt = 0; nt < 4; nt++) {
                const int n = wn * 32 + nt * 8 + (lane >> 2);
                bfr[nt][0] = fbits(Bb[n * ASTRIDE + kk + (lane & 3)]);
                bfr[nt][1] = fbits(Bb[n * ASTRIDE + kk + (lane & 3) + 4]);
            }
#pragma unroll
            for (int mt = 0; mt < 4; mt++)
#pragma unroll
                for (int nt = 0; nt < 4; nt++)
                    mma_tf32(acc[mt][nt], af[mt][0], af[mt][1], af[mt][2], af[mt][3],
                             bfr[nt][0], bfr[nt][1]);
        }
    }
    __syncthreads();   // safe smem reuse by caller (next phase / nothing)
}

// ------------------------- generic GEMM with bias (+optional ReLU) ----------
template<int RELU>
__launch_bounds__(256, 2)
__global__ void gemm_kernel(const float* __restrict__ A, long long asr,
                            const float* __restrict__ W,
                            const float* __restrict__ b1p, const float* __restrict__ b2p,
                            float* __restrict__ C, int M, int N, int K)
{
    extern __shared__ float sm[];
    float* As = sm;
    float* Bs = sm + 4 * STAGE_ELEMS;

    const int tid = threadIdx.x, lane = tid & 31, warp = tid >> 5;
    const int wm = warp >> 2, wn = warp & 3;
    const int mb = blockIdx.y * 128, nb = blockIdx.x * 128;

    float acc[4][4][4];
#pragma unroll
    for (int a = 0; a < 4; a++)
#pragma unroll
        for (int b = 0; b < 4; b++)
#pragma unroll
            for (int c = 0; c < 4; c++) acc[a][b][c] = 0.0f;

    run_gemm_acc(A, asr, M, mb, W + (size_t)nb * K, K, As, Bs, acc);

#pragma unroll
    for (int mt = 0; mt < 4; mt++) {
#pragma unroll
        for (int nt = 0; nt < 4; nt++) {
            const int row0 = mb + wm * 64 + mt * 16 + (lane >> 2);
            const int col  = nb + wn * 32 + nt * 8 + 2 * (lane & 3);
            const float b0v = (b1p ? b1p[col]     : 0.f) + (b2p ? b2p[col]     : 0.f);
            const float b1v = (b1p ? b1p[col + 1] : 0.f) + (b2p ? b2p[col + 1] : 0.f);
            float v0 = acc[mt][nt][0] + b0v, v1 = acc[mt][nt][1] + b1v;
            float v2 = acc[mt][nt][2] + b0v, v3 = acc[mt][nt][3] + b1v;
            if (RELU) {
                v0 = fmaxf(v0, 0.f); v1 = fmaxf(v1, 0.f);
                v2 = fmaxf(v2, 0.f); v3 = fmaxf(v3, 0.f);
            }
            if (row0 < M)     *(float2*)(C + (size_t)row0 * N + col)       = make_float2(v0, v1);
            if (row0 + 8 < M) *(float2*)(C + (size_t)(row0 + 8) * N + col) = make_float2(v2, v3);
        }
    }
}

// ------------------------- fused lstm1 step ----------------------------------
// h = sig(o) * tanh( sig(i) * tanh(g) ); f gate never computed (3/4 FLOPs).
// Grid: (HH/128, M/128). Sequential gate phases i -> g -> o, shared pipeline.
__launch_bounds__(256, 1)
__global__ void lstm1_kernel(const float* __restrict__ A, long long asr,
                             const float* __restrict__ W,
                             const float* __restrict__ bih, const float* __restrict__ bhh,
                             float* __restrict__ Hout, int M, int K)
{
    extern __shared__ float sm[];
    float* As = sm;
    float* Bs = sm + 4 * STAGE_ELEMS;

    const int tid = threadIdx.x, lane = tid & 31, warp = tid >> 5;
    const int wm = warp >> 2, wn = warp & 3;
    const int mb = blockIdx.y * 128, nb = blockIdx.x * 128;

    float keep[4][4][4];
    const int gset[3] = {0, 2, 3};   // i, g, o rows of W

#pragma unroll 1
    for (int ph = 0; ph < 3; ++ph) {
        const int g = gset[ph];
        float acc[4][4][4];
#pragma unroll
        for (int a = 0; a < 4; a++)
#pragma unroll
            for (int b = 0; b < 4; b++)
#pragma unroll
                for (int c = 0; c < 4; c++) acc[a][b][c] = 0.0f;

        run_gemm_acc(A, asr, M, mb, W + ((size_t)(g * HH + nb)) * K, K, As, Bs, acc);

#pragma unroll
        for (int mt = 0; mt < 4; mt++) {
#pragma unroll
            for (int nt = 0; nt < 4; nt++) {
                const int gcol = g * HH + nb + wn * 32 + nt * 8 + 2 * (lane & 3);
                const float b0 = bih[gcol] + bhh[gcol];
                const float b1 = bih[gcol + 1] + bhh[gcol + 1];
                if (ph == 0) {
                    keep[mt][nt][0] = sigf(acc[mt][nt][0] + b0);
                    keep[mt][nt][1] = sigf(acc[mt][nt][1] + b1);
                    keep[mt][nt][2] = sigf(acc[mt][nt][2] + b0);
                    keep[mt][nt][3] = sigf(acc[mt][nt][3] + b1);
                } else if (ph == 1) {
                    keep[mt][nt][0] *= tanhf(acc[mt][nt][0] + b0);
                    keep[mt][nt][1] *= tanhf(acc[mt][nt][1] + b1);
                    keep[mt][nt][2] *= tanhf(acc[mt][nt][2] + b0);
                    keep[mt][nt][3] *= tanhf(acc[mt][nt][3] + b1);
                } else {
                    const int row0 = mb + wm * 64 + mt * 16 + (lane >> 2);
                    const int colh = nb + wn * 32 + nt * 8 + 2 * (lane & 3);
                    const float v0 = sigf(acc[mt][nt][0] + b0) * tanhf(keep[mt][nt][0]);
                    const float v1 = sigf(acc[mt][nt][1] + b1) * tanhf(keep[mt][nt][1]);
                    const float v2 = sigf(acc[mt][nt][2] + b0) * tanhf(keep[mt][nt][2]);
                    const float v3 = sigf(acc[mt][nt][3] + b1) * tanhf(keep[mt][nt][3]);
                    *(float2*)(Hout + (size_t)row0 * HH + colh)       = make_float2(v0, v1);
                    *(float2*)(Hout + (size_t)(row0 + 8) * HH + colh) = make_float2(v2, v3);
                }
            }
        }
    }
}

// ------------------------- grid barrier (128 resident CTAs) -----------------
__device__ __forceinline__ void grid_bar()
{
    __threadfence();
    __syncthreads();
    if (threadIdx.x == 0) {
        const unsigned gen = g_sense;
        const unsigned arrived = atomicAdd((unsigned*)&g_cnt, 1u);
        if (arrived == NBLK_REC - 1u) {
            g_cnt = 0;
            __threadfence();
            atomicAdd((unsigned*)&g_sense, 1u);
        } else {
            while (g_sense == gen) { __nanosleep(32); }
        }
        __threadfence();
    }
    __syncthreads();
}

// ------------------------- recurrent LSTM layer ------------------------------
// 128 CTAs x 256 threads. CTA b owns h cols n0..n0+7 (32 gate cols).
// Whh slab persists in SMEM (tf32). Per step: h broadcast streamed as 16
// triple-buffered cp.async chunks (K=64 each) overlapped with the mma.
// c state lives in registers. One grid barrier per step.
__launch_bounds__(256, 1)
__global__ void recur_kernel(const float* __restrict__ xg,   // [BT, 4096]
                             const float* __restrict__ Whh,  // [4096, 1024]
                             float* __restrict__ hs,         // [BT, 1024]
                             float* __restrict__ hbuf)       // [2, 64, 1024]
{
    extern __shared__ float sm[];
    float* Ws = sm;                       // [32][1028]
    float* hS = sm + 32 * 1028;           // 3 * RC_BUFE
    float* gS = hS + RC_BUFE;             // [64][33] overlay on slot 1

    const int tid = threadIdx.x, lane = tid & 31, warp = tid >> 5;
    const int wm = warp >> 1, wn = warp & 1;     // 4(M) x 2(N)
    const int n0 = blockIdx.x * 8;

    // Whh slab: packed row c = g*8 + j  -> Whh[(g*HH + n0 + j)], tf32-rounded
#pragma unroll 1
    for (int c = 0; c < 32; c++) {
        const int g = c >> 3, j = c & 7;
        const float4 v = *(const float4*)(Whh + ((size_t)(g * HH + n0 + j)) * HH + tid * 4);
        float* d = Ws + c * 1028 + tid * 4;
        d[0] = tf32r(v.x); d[1] = tf32r(v.y); d[2] = tf32r(v.z); d[3] = tf32r(v.w);
    }
    __syncthreads();

    const int arow = wm * 16 + (lane >> 2);
    const int kofs = lane & 3;
    const int r0 = tid >> 3, j0 = tid & 7, r1 = 32 + (tid >> 3);
    float c0 = 0.f, c1 = 0.f;

    const uint32_t hS_sh = (uint32_t)__cvta_generic_to_shared(hS);

    for (int t = 0; t < TT; t++) {
        // prefetch this step's xg contributions (hidden under the mma)
        const size_t x0 = ((size_t)(r0 * TT + t)) * G4 + n0 + j0;
        const size_t x1 = ((size_t)(r1 * TT + t)) * G4 + n0 + j0;
        const float xi0 = xg[x0], xf0 = xg[x0 + 1024], xg0 = xg[x0 + 2048], xo0 = xg[x0 + 3072];
        const float xi1 = xg[x1], xf1 = xg[x1 + 1024], xg1 = xg[x1 + 2048], xo1 = xg[x1 + 3072];

        float acc[2][4] = {{0,0,0,0},{0,0,0,0}};

        if (t > 0) {
            const float* hsrc = hbuf + (size_t)(t & 1) * (BB * HH);

            auto issue = [&](int ch) {
                const int slot = ch % 3;
#pragma unroll
                for (int i = 0; i < 4; i++) {
                    const int v = tid + i * 256;
                    const int r = v >> 4, kseg = v & 15;
                    const float4* src = (const float4*)hsrc + (size_t)r * 256 + ch * 16 + kseg;
                    const uint32_t dst = hS_sh + (uint32_t)((slot * RC_BUFE + r * RC_PAD + kseg * 4) * 4);
                    cp16(dst, src);
                }
                cp_commit();
            };

            issue(0); issue(1);
#pragma unroll 1
            for (int ch = 0; ch < RC_CH; ++ch) {
                if (ch < RC_CH - 1) asm volatile("cp.async.wait_group 1;");
                else                asm volatile("cp.async.wait_group 0;");
                __syncthreads();
                if (ch + 2 < RC_CH) issue(ch + 2);

                const float* hb = hS + (ch % 3) * RC_BUFE;
#pragma unroll
                for (int ks = 0; ks < 8; ++ks) {
                    const int kk = ks * 8;
                    const uint32_t a0 = fbits(hb[arow * RC_PAD + kk + kofs]);
                    const uint32_t a1 = fbits(hb[(arow + 8) * RC_PAD + kk + kofs]);
                    const uint32_t a2 = fbits(hb[arow * RC_PAD + kk + kofs + 4]);
                    const uint32_t a3 = fbits(hb[(arow + 8) * RC_PAD + kk + kofs + 4]);
#pragma unroll
                    for (int nt = 0; nt < 2; nt++) {
                        const int ncol = wn * 16 + nt * 8 + (lane >> 2);
                        const int kg = ch * RC_CK + kk + kofs;
                        const uint32_t b0 = fbits(Ws[ncol * 1028 + kg]);
                        const uint32_t b1 = fbits(Ws[ncol * 1028 + kg + 4]);
                        mma_tf32(acc[nt], a0, a1, a2, a3, b0, b1);
                    }
                }
            }

            // gate exchange (gS overlays slot 1; last mma chunk used slot 0)
            {
                const int rr = wm * 16 + (lane >> 2);
#pragma unroll
                for (int nt = 0; nt < 2; nt++) {
                    const int cc = wn * 16 + nt * 8 + 2 * (lane & 3);
                    gS[rr * 33 + cc]           = acc[nt][0];
                    gS[rr * 33 + cc + 1]       = acc[nt][1];
                    gS[(rr + 8) * 33 + cc]     = acc[nt][2];
                    gS[(rr + 8) * 33 + cc + 1] = acc[nt][3];
                }
            }
            __syncthreads();
        }

        // gate combine + state update (c in registers)
        float gi0 = xi0, gf0 = xf0, gg0 = xg0, go0 = xo0;
        float gi1 = xi1, gf1 = xf1, gg1 = xg1, go1 = xo1;
        if (t > 0) {
            gi0 += gS[r0 * 33 + j0];      gf0 += gS[r0 * 33 + 8 + j0];
            gg0 += gS[r0 * 33 + 16 + j0]; go0 += gS[r0 * 33 + 24 + j0];
            gi1 += gS[r1 * 33 + j0];      gf1 += gS[r1 * 33 + 8 + j0];
            gg1 += gS[r1 * 33 + 16 + j0]; go1 += gS[r1 * 33 + 24 + j0];
        }
        c0 = sigf(gf0) * c0 + sigf(gi0) * tanhf(gg0);
        c1 = sigf(gf1) * c1 + sigf(gi1) * tanhf(gg1);
        const float h0v = sigf(go0) * tanhf(c0);
        const float h1v = sigf(go1) * tanhf(c1);

        float* hdst = hbuf + (size_t)((t + 1) & 1) * (BB * HH);
        hdst[r0 * HH + n0 + j0] = h0v;
        hdst[r1 * HH + n0 + j0] = h1v;
        hs[((size_t)(r0 * TT + t)) * HH + n0 + j0] = h0v;
        hs[((size_t)(r1 * TT + t)) * HH + n0 + j0] = h1v;

        if (t < TT - 1) grid_bar();
    }
}

// ------------------------- final MLP layer 3 ---------------------------------
__global__ void mlp3_kernel(const float* __restrict__ z2, const float* __restrict__ W3,
                            const float* __restrict__ b3, float* __restrict__ out)
{
    __shared__ float red[8];
    const int b = blockIdx.x;
    float s = 0.f;
    for (int k = threadIdx.x; k < 512; k += 256) s += z2[b * 512 + k] * W3[k];
#pragma unroll
    for (int o = 16; o; o >>= 1) s += __shfl_down_sync(0xffffffffu, s, o);
    if ((threadIdx.x & 31) == 0) red[threadIdx.x >> 5] = s;
    __syncthreads();
    if (threadIdx.x < 8) {
        s = red[threadIdx.x];
#pragma unroll
        for (int o = 4; o; o >>= 1) s += __shfl_down_sync(0xffu, s, o);
        if (threadIdx.x == 0) out[b] = s + b3[0];
    }
}

// ------------------------- launcher ------------------------------------------
extern "C" void kernel_launch(void* const* d_in, const int* in_sizes, int n_in,
                              void* d_out, int out_size)
{
    const float* xx       = (const float*)d_in[0];
    const float* l1_Wih0  = (const float*)d_in[1];
    const float* l1_bih0  = (const float*)d_in[2];
    const float* l1_bhh0  = (const float*)d_in[3];
    const float* l1_Wih1  = (const float*)d_in[4];
    const float* l1_bih1  = (const float*)d_in[5];
    const float* l1_bhh1  = (const float*)d_in[6];
    const float* l2_Wih0  = (const float*)d_in[7];
    const float* l2_Whh0  = (const float*)d_in[8];
    const float* l2_bih0  = (const float*)d_in[9];
    const float* l2_bhh0  = (const float*)d_in[10];
    const float* l2_Wih1  = (const float*)d_in[11];
    const float* l2_Whh1  = (const float*)d_in[12];
    const float* l2_bih1  = (const float*)d_in[13];
    const float* l2_bhh1  = (const float*)d_in[14];
    const float* mlp_W1   = (const float*)d_in[15];
    const float* mlp_b1   = (const float*)d_in[16];
    const float* mlp_W2   = (const float*)d_in[17];
    const float* mlp_b2   = (const float*)d_in[18];
    const float* mlp_W3   = (const float*)d_in[19];
    const float* mlp_b3   = (const float*)d_in[20];
    float* out = (float*)d_out;

    void* p;
    cudaGetSymbolAddress(&p, g_gates); float* gates = (float*)p;
    cudaGetSymbolAddress(&p, g_h1);    float* h1    = (float*)p;
    cudaGetSymbolAddress(&p, g_h2);    float* h2    = (float*)p;
    cudaGetSymbolAddress(&p, g_hbuf);  float* hbuf  = (float*)p;
    cudaGetSymbolAddress(&p, g_z1);    float* z1    = (float*)p;
    cudaGetSymbolAddress(&p, g_z2);    float* z2    = (float*)p;

    const int gemm_smem  = 8 * STAGE_ELEMS * 4;                       // 81920 B
    const int recur_smem = (32 * 1028 + 3 * RC_BUFE) * 4;             // 183808 B
    cudaFuncSetAttribute(gemm_kernel<0>, cudaFuncAttributeMaxDynamicSharedMemorySize, gemm_smem);
    cudaFuncSetAttribute(gemm_kernel<1>, cudaFuncAttributeMaxDynamicSharedMemorySize, gemm_smem);
    cudaFuncSetAttribute(lstm1_kernel,   cudaFuncAttributeMaxDynamicSharedMemorySize, gemm_smem);
    cudaFuncSetAttribute(recur_kernel,   cudaFuncAttributeMaxDynamicSharedMemorySize, recur_smem);

    const dim3 blk(256);

    // lstm1 (fused, f gate skipped): h = f(x @ W^T + b)
    lstm1_kernel<<<dim3(HH / 128, BT / 128), blk, gemm_smem>>>(xx, 256, l1_Wih0, l1_bih0, l1_bhh0, h1, BT, 256);
    lstm1_kernel<<<dim3(HH / 128, BT / 128), blk, gemm_smem>>>(h1, HH, l1_Wih1, l1_bih1, l1_bhh1, h2, BT, HH);

    // lstm2 layer 0: xg GEMM then recurrence
    gemm_kernel<0><<<dim3(G4 / 128, BT / 128), blk, gemm_smem>>>(h2, HH, l2_Wih0, l2_bih0, l2_bhh0, gates, BT, G4, HH);
    recur_kernel<<<NBLK_REC, blk, recur_smem>>>(gates, l2_Whh0, h1, hbuf);

    // lstm2 layer 1
    gemm_kernel<0><<<dim3(G4 / 128, BT / 128), blk, gemm_smem>>>(h1, HH, l2_Wih1, l2_bih1, l2_bhh1, gates, BT, G4, HH);
    recur_kernel<<<NBLK_REC, blk, recur_smem>>>(gates, l2_Whh1, h2, hbuf);

    // MLP on last timestep
    gemm_kernel<1><<<dim3(HH / 128, 1), blk, gemm_smem>>>(h2 + (size_t)(TT - 1) * HH, (long long)TT * HH,
                                                          mlp_W1, mlp_b1, nullptr, z1, BB, HH, HH);
    gemm_kernel<1><<<dim3((HH / 2) / 128, 1), blk, gemm_smem>>>(z1, HH, mlp_W2, mlp_b2, nullptr,
                                                                z2, BB, HH / 2, HH);
    mlp3_kernel<<<BB, blk>>>(z2, mlp_W3, mlp_b3, out);
}